// round 1
// baseline (speedup 1.0000x reference)
#include <cuda_runtime.h>
#include <math.h>

#define BH   64      // B*H
#define NB   32      // buckets
#define BSZ  128     // tokens per bucket
#define DHD  64      // head dim
#define TPB  (BSZ*DHD)   // 8192 floats per bucket tile

// Scratch (allocation-free rule: __device__ globals)
__device__ float g_R[BH*NB*NB];                       // 256 KB
__device__ float g_kre[(size_t)BH*NB*BSZ*DHD];        // 64 MB
__device__ float g_vre[(size_t)BH*NB*BSZ*DHD];        // 64 MB

// ---------------------------------------------------------------------------
// Kernel 1: bucket key sums -> routing logits -> 7 Sinkhorn iters -> exp ->
// strictly-lower-triangular R.  One block per bh, 1024 threads = (u,j) grid.
// ---------------------------------------------------------------------------
__global__ void __launch_bounds__(1024)
sinkhorn_kernel(const float* __restrict__ k,
                const float* __restrict__ sort_w,
                const float* __restrict__ gum)
{
    int bh  = blockIdx.x;
    int tid = threadIdx.x;

    __shared__ float bkr[NB][DHD];      // bucket key sums (32x64)
    __shared__ float ews[DHD][NB];      // sort_w slice   (64x32)
    __shared__ float smx[NB][NB + 1];   // column-reduction scratch

    // bucket sums: 2048 (u,d) sums, 2 per thread, each over 128 tokens
    #pragma unroll
    for (int rep = 0; rep < 2; rep++) {
        int idx = tid + rep * 1024;
        int u = idx >> 6, d = idx & 63;
        const float* kp = k + (size_t)bh * NB * TPB + (size_t)u * TPB + d;
        float s = 0.f;
        #pragma unroll 8
        for (int t = 0; t < BSZ; t++) s += kp[t * DHD];
        bkr[u][d] = s;
    }
    // load e_w for this head (sort_w broadcast over batch: h = bh % 16)
    int h = bh & 15;
    #pragma unroll
    for (int rep = 0; rep < 2; rep++) {
        int idx = tid + rep * 1024;
        ((float*)ews)[idx] = sort_w[h * (DHD * NB) + idx];
    }
    __syncthreads();

    int u = tid >> 5;   // row (warp == row)
    int j = tid & 31;   // col (lane)

    // logits
    float r = 0.f;
    #pragma unroll
    for (int d = 0; d < DHD; d++) r += bkr[u][d] * ews[d][j];
    r = logf(fmaxf(r, 0.f) + 1e-6f);
    r = (r + gum[bh * 1024 + tid]) * (1.0f / 0.75f);

    // 7 Sinkhorn iterations: row LSE (axis=2, over j) then col LSE (axis=1, over u)
    for (int it = 0; it < 7; it++) {
        // row logsumexp via warp shuffles
        float m = r;
        #pragma unroll
        for (int off = 16; off > 0; off >>= 1)
            m = fmaxf(m, __shfl_xor_sync(0xffffffffu, m, off));
        float se = __expf(r - m);
        #pragma unroll
        for (int off = 16; off > 0; off >>= 1)
            se += __shfl_xor_sync(0xffffffffu, se, off);
        r -= m + logf(se);

        // column logsumexp via smem
        smx[u][j] = r;
        __syncthreads();
        float cm = -3.0e38f;
        #pragma unroll
        for (int vv = 0; vv < NB; vv++) cm = fmaxf(cm, smx[vv][j]);
        float cs = 0.f;
        #pragma unroll
        for (int vv = 0; vv < NB; vv++) cs += __expf(smx[vv][j] - cm);
        r -= cm + logf(cs);
        __syncthreads();
    }

    r = __expf(r);
    if (j >= u) r = 0.f;           // tril(R, -1): strictly earlier buckets only
    g_R[bh * 1024 + tid] = r;
}

// ---------------------------------------------------------------------------
// Kernel 2: soft permutation  k_re = R @ Kmat, v_re = R @ Vmat  (per bh:
// 32x32 @ 32x8192).  Block = (col-tile of 256, bh); all 32 output rows per
// block so K/V are read exactly once.  Triangular inner loop (R strict-lower).
// ---------------------------------------------------------------------------
__global__ void __launch_bounds__(256)
permute_kernel(const float* __restrict__ k, const float* __restrict__ v)
{
    int tilec = blockIdx.x;   // 0..31 (256-column tiles of the 8192-wide Kmat)
    int bh    = blockIdx.y;
    int c     = threadIdx.x;  // 0..255

    __shared__ float Rs[NB][NB];
    __shared__ float T[NB][256];

    #pragma unroll
    for (int rep = 0; rep < 4; rep++)
        ((float*)Rs)[c + rep * 256] = g_R[bh * 1024 + c + rep * 256];

    size_t base = (size_t)bh * NB * TPB + (size_t)tilec * 256 + c;

    // ---- K ----
    #pragma unroll
    for (int vv = 0; vv < NB; vv++) T[vv][c] = k[base + (size_t)vv * TPB];
    __syncthreads();

    float acc[NB];
    #pragma unroll
    for (int uu = 0; uu < NB; uu++) acc[uu] = 0.f;
    #pragma unroll
    for (int vv = 0; vv < NB; vv++) {
        float x = T[vv][c];
        #pragma unroll
        for (int uu = vv + 1; uu < NB; uu++) acc[uu] += Rs[uu][vv] * x;
    }
    #pragma unroll
    for (int uu = 0; uu < NB; uu++) g_kre[base + (size_t)uu * TPB] = acc[uu];
    __syncthreads();

    // ---- V ----
    #pragma unroll
    for (int vv = 0; vv < NB; vv++) T[vv][c] = v[base + (size_t)vv * TPB];
    __syncthreads();

    #pragma unroll
    for (int uu = 0; uu < NB; uu++) acc[uu] = 0.f;
    #pragma unroll
    for (int vv = 0; vv < NB; vv++) {
        float x = T[vv][c];
        #pragma unroll
        for (int uu = vv + 1; uu < NB; uu++) acc[uu] += Rs[uu][vv] * x;
    }
    #pragma unroll
    for (int uu = 0; uu < NB; uu++) g_vre[base + (size_t)uu * TPB] = acc[uu];
}

// ---------------------------------------------------------------------------
// Kernel 3: per-(bh, bucket) attention.  128 queries x 256 keys x 64 dims.
// Key/value = [k_re(bucket) ; k(bucket)] (order matches reference concat; the
// softmax is order-invariant anyway).  One query per thread, flash-style
// online softmax in 8-key groups, K/V tiles (64 keys) staged in smem.
// ---------------------------------------------------------------------------
__global__ void __launch_bounds__(128)
attn_kernel(const float* __restrict__ q,
            const float* __restrict__ k,
            const float* __restrict__ v,
            float* __restrict__ out)
{
    int u  = blockIdx.x;   // bucket
    int bh = blockIdx.y;
    int i  = threadIdx.x;  // query 0..127

    const size_t base = (size_t)bh * NB * TPB + (size_t)u * TPB;

    __shared__ float Ks[64][DHD];
    __shared__ float Vs[64][DHD];

    // load this thread's query row (64 floats) into registers
    float4 qr[16];
    const float4* qp = (const float4*)(q + base + (size_t)i * DHD);
    #pragma unroll
    for (int d = 0; d < 16; d++) qr[d] = qp[d];

    float o[DHD];
    #pragma unroll
    for (int d = 0; d < DHD; d++) o[d] = 0.f;
    float m = -3.0e38f, l = 0.f;

    for (int tile = 0; tile < 4; tile++) {
        // tiles 0,1 = soft-permuted keys (k_re/v_re); tiles 2,3 = own bucket
        const float* ksrc;
        const float* vsrc;
        if (tile < 2) {
            size_t off = (size_t)bh * NB * TPB + (size_t)u * TPB + (size_t)tile * 64 * DHD;
            ksrc = g_kre + off;
            vsrc = g_vre + off;
        } else {
            size_t off = base + (size_t)(tile - 2) * 64 * DHD;
            ksrc = k + off;
            vsrc = v + off;
        }
        __syncthreads();
        const float4* kp4 = (const float4*)ksrc;
        const float4* vp4 = (const float4*)vsrc;
        float4* Ks4 = (float4*)Ks;
        float4* Vs4 = (float4*)Vs;
        #pragma unroll
        for (int r = 0; r < 8; r++) {
            Ks4[i + r * 128] = kp4[i + r * 128];
            Vs4[i + r * 128] = vp4[i + r * 128];
        }
        __syncthreads();

        for (int jj = 0; jj < 64; jj += 8) {
            float s[8];
            #pragma unroll
            for (int a = 0; a < 8; a++) {
                const float4* krow = (const float4*)Ks[jj + a];
                float acc = 0.f;
                #pragma unroll
                for (int d = 0; d < 16; d++) {
                    float4 kk = krow[d];
                    acc += qr[d].x * kk.x + qr[d].y * kk.y
                         + qr[d].z * kk.z + qr[d].w * kk.w;
                }
                s[a] = acc * 0.03125f;   // DIM^-0.5 = 1024^-0.5 = 1/32
            }
            float mt = s[0];
            #pragma unroll
            for (int a = 1; a < 8; a++) mt = fmaxf(mt, s[a]);
            float mnew = fmaxf(m, mt);
            float corr = __expf(m - mnew);
            l *= corr;
            #pragma unroll
            for (int d = 0; d < DHD; d++) o[d] *= corr;
            float p[8];
            #pragma unroll
            for (int a = 0; a < 8; a++) { p[a] = __expf(s[a] - mnew); l += p[a]; }
            m = mnew;
            #pragma unroll
            for (int a = 0; a < 8; a++) {
                const float4* vrow = (const float4*)Vs[jj + a];
                #pragma unroll
                for (int d = 0; d < 16; d++) {
                    float4 vv = vrow[d];
                    o[4*d+0] += p[a] * vv.x;
                    o[4*d+1] += p[a] * vv.y;
                    o[4*d+2] += p[a] * vv.z;
                    o[4*d+3] += p[a] * vv.w;
                }
            }
        }
    }

    float inv = 1.f / l;
    float4* op = (float4*)(out + base + (size_t)i * DHD);
    #pragma unroll
    for (int d = 0; d < 16; d++) {
        float4 t;
        t.x = o[4*d+0] * inv;
        t.y = o[4*d+1] * inv;
        t.z = o[4*d+2] * inv;
        t.w = o[4*d+3] * inv;
        op[d] = t;
    }
}

// ---------------------------------------------------------------------------
extern "C" void kernel_launch(void* const* d_in, const int* in_sizes, int n_in,
                              void* d_out, int out_size)
{
    const float* q   = (const float*)d_in[0];
    const float* k   = (const float*)d_in[1];
    const float* v   = (const float*)d_in[2];
    const float* sw  = (const float*)d_in[3];
    const float* gum = (const float*)d_in[4];
    float* out = (float*)d_out;

    sinkhorn_kernel<<<BH, 1024>>>(k, sw, gum);

    dim3 g2(NB, BH);           // 32 column-tiles x 64 bh
    permute_kernel<<<g2, 256>>>(k, v);

    dim3 g3(NB, BH);           // 32 buckets x 64 bh
    attn_kernel<<<g3, 128>>>(q, k, v, out);
}